// round 11
// baseline (speedup 1.0000x reference)
#include <cuda_runtime.h>
#include <math.h>

// ---------------- problem constants ----------------
#define B_SZ   16
#define C_DIM  512
#define WS     7
#define NH     16
#define HD     32
#define HID    2048
#define NTOK   49
#define NWIN   64
#define M_TOK  50176
#define SCALE_F 0.17677669529663687f

// ---------------- scratch (device globals; no allocation) ----------------
__device__ float g_h[25690112];
__device__ float g_q[25690112];
__device__ float g_k[25690112];
__device__ float g_v[25690112];
__device__ float g_attn[25690112];
__device__ float g_act[102760448];

// ---------------- LayerNorm ----------
__global__ void __launch_bounds__(128) ln_kernel(
    const float* __restrict__ x, const float* __restrict__ gw,
    const float* __restrict__ bw, float* __restrict__ out)
{
    __shared__ float red[8];
    int row = blockIdx.x;
    int tid = threadIdx.x;
    const float4* xr = reinterpret_cast<const float4*>(x + (size_t)row * C_DIM);
    float4 v = xr[tid];
    float s  = v.x + v.y + v.z + v.w;
    float ss = v.x*v.x + v.y*v.y + v.z*v.z + v.w*v.w;
    #pragma unroll
    for (int o = 16; o > 0; o >>= 1) {
        s  += __shfl_xor_sync(0xFFFFFFFFu, s,  o);
        ss += __shfl_xor_sync(0xFFFFFFFFu, ss, o);
    }
    int warp = tid >> 5;
    if ((tid & 31) == 0) { red[warp] = s; red[4 + warp] = ss; }
    __syncthreads();
    float st  = red[0] + red[1] + red[2] + red[3];
    float sst = red[4] + red[5] + red[6] + red[7];
    float mu  = st * (1.0f / C_DIM);
    float var = sst * (1.0f / C_DIM) - mu * mu;
    float inv = rsqrtf(var + 1e-5f);
    float4 gv = reinterpret_cast<const float4*>(gw)[tid];
    float4 bv = reinterpret_cast<const float4*>(bw)[tid];
    float4 o;
    o.x = (v.x - mu) * inv * gv.x + bv.x;
    o.y = (v.y - mu) * inv * gv.y + bv.y;
    o.z = (v.z - mu) * inv * gv.z + bv.z;
    o.w = (v.w - mu) * inv * gv.w + bv.w;
    reinterpret_cast<float4*>(out + (size_t)row * C_DIM)[tid] = o;
}

// ---------------- tf32 tensor-core GEMM 128x128, 128 thr, 64x64 warp tile --
#define BM 128
#define BN 128
#define BKT 16

#define MODE_QKV  0
#define MODE_PROJ 1
#define MODE_FC1  2
#define MODE_FC2  3

__device__ __forceinline__ float f2tf32(float f) {
    unsigned r;
    asm("cvt.rna.tf32.f32 %0, %1;" : "=r"(r) : "f"(f));
    return __uint_as_float(r);
}

__device__ __forceinline__ int swz(int row) {   // bank swizzle selector 0..3
    return (row ^ (row >> 2)) & 3;
}

__device__ __forceinline__ void mma_tf32(
    float& c0, float& c1, float& c2, float& c3,
    float a0, float a1, float a2, float a3,
    float b0, float b1)
{
    asm volatile(
        "mma.sync.aligned.m16n8k8.row.col.f32.tf32.tf32.f32 "
        "{%0,%1,%2,%3}, {%4,%5,%6,%7}, {%8,%9}, {%0,%1,%2,%3};"
        : "+f"(c0), "+f"(c1), "+f"(c2), "+f"(c3)
        : "r"(__float_as_uint(a0)), "r"(__float_as_uint(a1)),
          "r"(__float_as_uint(a2)), "r"(__float_as_uint(a3)),
          "r"(__float_as_uint(b0)), "r"(__float_as_uint(b1)));
}

// smem layout: tile[row][16] where the 16 k-values of a chunk are stored
// permuted (pos = 4*(k&3) + (k>>2)) and 16B-slot-swizzled by swz(row).
// A lane then fetches its whole fragment-k set {tig, tig+4, tig+8, tig+12}
// with ONE conflict-free LDS.128.

template<int MODE>
__global__ void __launch_bounds__(128) tgemm_kernel(
    const float* __restrict__ A,     // M x K (row major)
    const float* __restrict__ W,     // K x Ncols (row major)
    const float* __restrict__ bias,
    const float* __restrict__ resid,
    float* __restrict__ out,
    int K, int Ncols)
{
    __shared__ __align__(16) float As[2][BM][16];
    __shared__ __align__(16) float Bs[2][BN][16];

    int tid  = threadIdx.x;
    int lane = tid & 31;
    int warp = tid >> 5;
    int gq   = lane >> 2;     // 0..7
    int tig  = lane & 3;      // 0..3
    int wm   = warp >> 1;     // 0..1 (64 rows)
    int wn   = warp & 1;      // 0..1 (64 cols)
    int m0 = blockIdx.y * BM;
    int n0 = blockIdx.x * BN;

    float acc[4][8][4];
    #pragma unroll
    for (int i = 0; i < 4; i++)
        #pragma unroll
        for (int j = 0; j < 8; j++)
            #pragma unroll
            for (int c = 0; c < 4; c++) acc[i][j][c] = 0.0f;

    const float* Aptr = A + (size_t)m0 * K + (size_t)tid * K;  // thread = one A row
    const float* Wptr = W + n0;

    // B load slots: float4 f = tid*4+i  ->  k-row f>>5, col4 (f&31)*4
    int bkr[4], bnc[4];
    #pragma unroll
    for (int i = 0; i < 4; i++) {
        int f = tid * 4 + i;
        bkr[i] = f >> 5;
        bnc[i] = (f & 31) * 4;
    }

    float4 pa[4], pb[4];

    auto fetch = [&](int k0) {
        #pragma unroll
        for (int i = 0; i < 4; i++)
            pa[i] = *reinterpret_cast<const float4*>(Aptr + k0 + 4 * i);
        #pragma unroll
        for (int i = 0; i < 4; i++)
            pb[i] = *reinterpret_cast<const float4*>(Wptr + (size_t)(k0 + bkr[i]) * Ncols + bnc[i]);
    };

    auto stage = [&](int buf) {
        int sA = swz(tid);
        #pragma unroll
        for (int i = 0; i < 4; i++) {         // original k = 4i + e
            float vv[4] = {pa[i].x, pa[i].y, pa[i].z, pa[i].w};
            #pragma unroll
            for (int e = 0; e < 4; e++)
                As[buf][tid][4 * (e ^ sA) + i] = f2tf32(vv[e]);
        }
        #pragma unroll
        for (int i = 0; i < 4; i++) {         // k-row bkr[i], cols bnc[i]+e
            float vv[4] = {pb[i].x, pb[i].y, pb[i].z, pb[i].w};
            int kr = bkr[i];
            #pragma unroll
            for (int e = 0; e < 4; e++) {
                int n = bnc[i] + e;
                Bs[buf][n][4 * ((kr & 3) ^ swz(n)) + (kr >> 2)] = f2tf32(vv[e]);
            }
        }
    };

    auto compute = [&](int buf) {
        float4 af0[4], af1[4];
        #pragma unroll
        for (int mt = 0; mt < 4; mt++) {
            int r0 = wm * 64 + mt * 16 + gq;
            int r1 = r0 + 8;
            af0[mt] = *reinterpret_cast<const float4*>(&As[buf][r0][4 * (tig ^ swz(r0))]);
            af1[mt] = *reinterpret_cast<const float4*>(&As[buf][r1][4 * (tig ^ swz(r1))]);
        }
        #pragma unroll
        for (int half = 0; half < 2; half++) {
            float4 bf[4];
            #pragma unroll
            for (int q = 0; q < 4; q++) {
                int nt = half * 4 + q;
                int nc = wn * 64 + nt * 8 + gq;
                bf[q] = *reinterpret_cast<const float4*>(&Bs[buf][nc][4 * (tig ^ swz(nc))]);
            }
            #pragma unroll
            for (int mt = 0; mt < 4; mt++) {
                #pragma unroll
                for (int q = 0; q < 4; q++) {
                    int nt = half * 4 + q;
                    // k-step 0: components .x (k=tig), .y (k=tig+4)
                    mma_tf32(acc[mt][nt][0], acc[mt][nt][1], acc[mt][nt][2], acc[mt][nt][3],
                             af0[mt].x, af1[mt].x, af0[mt].y, af1[mt].y,
                             bf[q].x, bf[q].y);
                    // k-step 1: components .z (k=tig+8), .w (k=tig+12)
                    mma_tf32(acc[mt][nt][0], acc[mt][nt][1], acc[mt][nt][2], acc[mt][nt][3],
                             af0[mt].z, af1[mt].z, af0[mt].w, af1[mt].w,
                             bf[q].z, bf[q].w);
                }
            }
        }
    };

    fetch(0);
    stage(0);
    __syncthreads();
    int buf = 0;
    for (int k0 = BKT; k0 <= K; k0 += BKT) {
        bool has = (k0 < K);
        if (has) fetch(k0);
        compute(buf);
        if (has) {
            stage(buf ^ 1);
            __syncthreads();
            buf ^= 1;
        }
    }

    // ---------------- epilogues ----------------
    #pragma unroll
    for (int mt = 0; mt < 4; mt++) {
        #pragma unroll
        for (int hh = 0; hh < 2; hh++) {
            int row = m0 + wm * 64 + mt * 16 + gq + hh * 8;
            if (MODE == MODE_QKV) {
                int bb = row / 3136;
                int l  = row - bb * 3136;
                int hr = l / 56;
                int wc = l - hr * 56;
                int gwin = bb * NWIN + (hr / WS) * 8 + (wc / WS);
                int n  = (hr % WS) * WS + (wc % WS);
                size_t ob = (size_t)gwin * (NH * NTOK * HD) + (size_t)n * HD;
                #pragma unroll
                for (int nt = 0; nt < 8; nt++) {
                    int col = n0 + wn * 64 + nt * 8 + 2 * tig;
                    float v0 = acc[mt][nt][2 * hh];
                    float v1 = acc[mt][nt][2 * hh + 1];
                    int head = col >> 5, d = col & 31;
                    out[ob + (size_t)head * (NTOK * HD) + d]     = v0 + bias[col];
                    out[ob + (size_t)head * (NTOK * HD) + d + 1] = v1 + bias[col + 1];
                }
            } else {
                size_t ro = (size_t)row * Ncols;
                #pragma unroll
                for (int nt = 0; nt < 8; nt++) {
                    int col = n0 + wn * 64 + nt * 8 + 2 * tig;
                    float v0 = acc[mt][nt][2 * hh];
                    float v1 = acc[mt][nt][2 * hh + 1];
                    if (MODE == MODE_PROJ) {
                        out[ro + col]     = v0 + bias[col]     + resid[ro + col];
                        out[ro + col + 1] = v1 + bias[col + 1] + resid[ro + col + 1];
                    } else if (MODE == MODE_FC1) {
                        float a0 = v0 + bias[col];
                        float a1 = v1 + bias[col + 1];
                        out[ro + col]     = 0.5f * a0 * (1.0f + erff(a0 * 0.70710678118654752f));
                        out[ro + col + 1] = 0.5f * a1 * (1.0f + erff(a1 * 0.70710678118654752f));
                    } else { // FC2
                        out[ro + col]     = resid[ro + col]     + v0 + bias[col];
                        out[ro + col + 1] = resid[ro + col + 1] + v1 + bias[col + 1];
                    }
                }
            }
        }
    }
}

// ---------------- attention: one block per (head, window) ----------------
__global__ void __launch_bounds__(128) attn_kernel(
    const float* __restrict__ q, const float* __restrict__ k,
    const float* __restrict__ v, const float* __restrict__ rb,
    float* __restrict__ out)
{
    __shared__ float qs[NTOK * 33];
    __shared__ float ks[NTOK * 33];
    __shared__ float vs[NTOK * 33];
    __shared__ float S[NTOK * NTOK];

    int head = blockIdx.x;
    int g    = blockIdx.y;
    int tid  = threadIdx.x;
    size_t base = ((size_t)g * NH + head) * (NTOK * HD);

    for (int i = tid; i < NTOK * HD; i += 128) {
        int n = i >> 5, d = i & 31;
        qs[n * 33 + d] = q[base + i];
        ks[n * 33 + d] = k[base + i];
        vs[n * 33 + d] = v[base + i];
    }
    __syncthreads();

    const float* rbh = rb + (size_t)head * NTOK * NTOK;
    for (int idx = tid; idx < NTOK * NTOK; idx += 128) {
        int n = idx / NTOK, m = idx - n * NTOK;
        float acc = 0.0f;
        #pragma unroll
        for (int d = 0; d < HD; d++)
            acc = fmaf(qs[n * 33 + d], ks[m * 33 + d], acc);
        S[idx] = acc * SCALE_F + rbh[idx];
    }
    __syncthreads();

    if (tid < NTOK) {
        float mx = -1e30f;
        #pragma unroll 7
        for (int m = 0; m < NTOK; m++) mx = fmaxf(mx, S[tid * NTOK + m]);
        float sum = 0.0f;
        #pragma unroll 7
        for (int m = 0; m < NTOK; m++) {
            float e = __expf(S[tid * NTOK + m] - mx);
            S[tid * NTOK + m] = e;
            sum += e;
        }
        float r = 1.0f / sum;
        #pragma unroll 7
        for (int m = 0; m < NTOK; m++) S[tid * NTOK + m] *= r;
    }
    __syncthreads();

    int bb = g >> 6;
    int wi = g & 63;
    int hr0 = (wi >> 3) * WS, wc0 = (wi & 7) * WS;
    for (int idx = tid; idx < NTOK * HD; idx += 128) {
        int n = idx >> 5, d = idx & 31;
        float acc = 0.0f;
        #pragma unroll 7
        for (int m = 0; m < NTOK; m++)
            acc = fmaf(S[n * NTOK + m], vs[m * 33 + d], acc);
        int hr = hr0 + n / WS, wc = wc0 + n % WS;
        size_t t = (size_t)bb * 3136 + (size_t)hr * 56 + wc;
        out[t * C_DIM + head * HD + d] = acc;
    }
}

// ---------------- launch ----------------
extern "C" void kernel_launch(void* const* d_in, const int* in_sizes, int n_in,
                              void* d_out, int out_size)
{
    const float* x    = (const float*)d_in[0];
    const float* Wq   = (const float*)d_in[1];
    const float* bq   = (const float*)d_in[2];
    const float* Wk   = (const float*)d_in[3];
    const float* bk   = (const float*)d_in[4];
    const float* Wv   = (const float*)d_in[5];
    const float* bv   = (const float*)d_in[6];
    const float* Wp   = (const float*)d_in[7];
    const float* bp   = (const float*)d_in[8];
    const float* rbias= (const float*)d_in[9];
    const float* g1   = (const float*)d_in[10];
    const float* b1   = (const float*)d_in[11];
    const float* g2   = (const float*)d_in[12];
    const float* b2   = (const float*)d_in[13];
    const float* W1   = (const float*)d_in[14];
    const float* bfc1 = (const float*)d_in[15];
    const float* W2   = (const float*)d_in[16];
    const float* bfc2 = (const float*)d_in[17];
    float* out = (float*)d_out;

    float *h, *q, *k, *v, *attn, *act;
    cudaGetSymbolAddress((void**)&h,    g_h);
    cudaGetSymbolAddress((void**)&q,    g_q);
    cudaGetSymbolAddress((void**)&k,    g_k);
    cudaGetSymbolAddress((void**)&v,    g_v);
    cudaGetSymbolAddress((void**)&attn, g_attn);
    cudaGetSymbolAddress((void**)&act,  g_act);

    dim3 gemm512(4, M_TOK / BM);
    dim3 gemm2048(16, M_TOK / BM);
    dim3 attn_grid(NH, B_SZ * NWIN);

    ln_kernel<<<M_TOK, 128>>>(x, g1, b1, h);
    tgemm_kernel<MODE_QKV><<<gemm512, 128>>>(h, Wq, bq, nullptr, q, C_DIM, C_DIM);
    tgemm_kernel<MODE_QKV><<<gemm512, 128>>>(h, Wk, bk, nullptr, k, C_DIM, C_DIM);
    tgemm_kernel<MODE_QKV><<<gemm512, 128>>>(h, Wv, bv, nullptr, v, C_DIM, C_DIM);
    attn_kernel<<<attn_grid, 128>>>(q, k, v, rbias, attn);
    tgemm_kernel<MODE_PROJ><<<gemm512, 128>>>(attn, Wp, bp, x, out, C_DIM, C_DIM);
    ln_kernel<<<M_TOK, 128>>>(out, g2, b2, h);
    tgemm_kernel<MODE_FC1><<<gemm2048, 128>>>(h, W1, bfc1, nullptr, act, C_DIM, HID);
    tgemm_kernel<MODE_FC2><<<gemm512, 128>>>(act, W2, bfc2, out, out, HID, C_DIM);
}

// round 13
// speedup vs baseline: 1.5308x; 1.5308x over previous
#include <cuda_runtime.h>
#include <math.h>
#include <stdint.h>

// ---------------- problem constants ----------------
#define B_SZ   16
#define C_DIM  512
#define WS     7
#define NH     16
#define HD     32
#define HID    2048
#define NTOK   49
#define NWIN   64
#define M_TOK  50176
#define SCALE_F 0.17677669529663687f

// k-permutation within each 16-block: value for logical k stored at
// position p(k) = 4*(k&3) + ((k>>2)&3).  Applied identically to A-cols and
// B-cols by all producers, so GEMM fragment float4 loads are contiguous.
#define KPERM(c) (((c) & ~15) + 4 * ((c) & 3) + (((c) >> 2) & 3))

// ---------------- scratch (device globals; no allocation) ----------------
__device__ float g_h[25690112];
__device__ float g_q[25690112];
__device__ float g_k[25690112];
__device__ float g_v[25690112];
__device__ float g_attn[25690112];
__device__ float g_act[102760448];
__device__ float g_wq[262144], g_wk[262144], g_wv[262144], g_wp[262144];
__device__ float g_w1t[1048576];   // [2048][512]
__device__ float g_w2t[1048576];   // [512][2048]

__device__ __forceinline__ float f2tf32(float f) {
    unsigned r;
    asm("cvt.rna.tf32.f32 %0, %1;" : "=r"(r) : "f"(f));
    return __uint_as_float(r);
}

// ---------------- LayerNorm: tf32-rounded, k-permuted output -------------
__global__ void __launch_bounds__(128) ln_kernel(
    const float* __restrict__ x, const float* __restrict__ gw,
    const float* __restrict__ bw, float* __restrict__ out)
{
    __shared__ float red[8];
    int row = blockIdx.x;
    int tid = threadIdx.x;
    const float4* xr = reinterpret_cast<const float4*>(x + (size_t)row * C_DIM);
    float4 v = xr[tid];
    float s  = v.x + v.y + v.z + v.w;
    float ss = v.x*v.x + v.y*v.y + v.z*v.z + v.w*v.w;
    #pragma unroll
    for (int o = 16; o > 0; o >>= 1) {
        s  += __shfl_xor_sync(0xFFFFFFFFu, s,  o);
        ss += __shfl_xor_sync(0xFFFFFFFFu, ss, o);
    }
    int warp = tid >> 5;
    if ((tid & 31) == 0) { red[warp] = s; red[4 + warp] = ss; }
    __syncthreads();
    float st  = red[0] + red[1] + red[2] + red[3];
    float sst = red[4] + red[5] + red[6] + red[7];
    float mu  = st * (1.0f / C_DIM);
    float var = sst * (1.0f / C_DIM) - mu * mu;
    float inv = rsqrtf(var + 1e-5f);
    float4 gv = reinterpret_cast<const float4*>(gw)[tid];
    float4 bv = reinterpret_cast<const float4*>(bw)[tid];
    float o[4];
    o[0] = f2tf32((v.x - mu) * inv * gv.x + bv.x);
    o[1] = f2tf32((v.y - mu) * inv * gv.y + bv.y);
    o[2] = f2tf32((v.z - mu) * inv * gv.z + bv.z);
    o[3] = f2tf32((v.w - mu) * inv * gv.w + bv.w);
    int c0 = tid * 4;                       // c0..c0+3, same (c>>2) group
    int base = c0 & ~15;
    int j = (c0 >> 2) & 3;
    float* orow = out + (size_t)row * C_DIM + base + j;
    #pragma unroll
    for (int e = 0; e < 4; e++) orow[4 * e] = o[e];   // pos = base + 4e + j
}

// ---------------- transpose W (K x N) -> Wt (N x K), permuted+rounded ----
__global__ void __launch_bounds__(256) transpose_kernel(
    const float* __restrict__ src, float* __restrict__ dst, int R, int C)
{
    __shared__ float t[32][33];
    int bx = blockIdx.x * 32, by = blockIdx.y * 32;
    int tx = threadIdx.x & 31;
    int ty4 = (threadIdx.x >> 5) * 4;
    #pragma unroll
    for (int i = 0; i < 4; i++)
        t[ty4 + i][tx] = src[(size_t)(by + ty4 + i) * C + bx + tx];
    __syncthreads();
    #pragma unroll
    for (int i = 0; i < 4; i++) {
        int kk = by + tx;                       // k index (contiguous in tx)
        dst[(size_t)(bx + ty4 + i) * R + KPERM(kk)] = f2tf32(t[tx][ty4 + i]);
    }
}

// ---------------- tf32 mma GEMM: 256x128 block, 8 warps x (64x64) --------
#define BMT 256
#define BNT 128
#define BKT 16

#define MODE_QKV  0
#define MODE_PROJ 1
#define MODE_FC1  2
#define MODE_FC2  3

// dynamic smem floats: As[2][256][16] then Bs[2][128][16]
#define A_FLOATS 4096      // per buffer
#define B_FLOATS 2048
#define SMEM_GEMM_BYTES ((2 * A_FLOATS + 2 * B_FLOATS) * 4)

__device__ __forceinline__ uint32_t smem_u32(const void* p) {
    uint32_t a;
    asm("{ .reg .u64 t; cvta.to.shared.u64 t, %1; cvt.u32.u64 %0, t; }"
        : "=r"(a) : "l"(p));
    return a;
}

__device__ __forceinline__ void mma_tf32(
    float& c0, float& c1, float& c2, float& c3,
    float a0, float a1, float a2, float a3,
    float b0, float b1)
{
    asm volatile(
        "mma.sync.aligned.m16n8k8.row.col.f32.tf32.tf32.f32 "
        "{%0,%1,%2,%3}, {%4,%5,%6,%7}, {%8,%9}, {%0,%1,%2,%3};"
        : "+f"(c0), "+f"(c1), "+f"(c2), "+f"(c3)
        : "r"(__float_as_uint(a0)), "r"(__float_as_uint(a1)),
          "r"(__float_as_uint(a2)), "r"(__float_as_uint(a3)),
          "r"(__float_as_uint(b0)), "r"(__float_as_uint(b1)));
}

template<int MODE>
__global__ void __launch_bounds__(256) tgemm_kernel(
    const float* __restrict__ A,      // M x K (tf32-rounded, k-permuted)
    const float* __restrict__ Bt,     // Ncols x K (tf32-rounded, k-permuted)
    const float* __restrict__ bias,
    const float* __restrict__ resid,
    float* __restrict__ out,
    int K, int Ncols)
{
    extern __shared__ float sm[];
    uint32_t smb = smem_u32(sm);

    int tid  = threadIdx.x;
    int lane = tid & 31;
    int warp = tid >> 5;
    int gq   = lane >> 2;     // 0..7
    int tig  = lane & 3;      // 0..3
    int wm   = warp >> 1;     // 0..3 (64 rows each)
    int wn   = warp & 1;      // 0..1 (64 cols each)
    int m0 = blockIdx.y * BMT;
    int n0 = blockIdx.x * BNT;

    float acc[4][8][4];
    #pragma unroll
    for (int i = 0; i < 4; i++)
        #pragma unroll
        for (int j = 0; j < 8; j++)
            #pragma unroll
            for (int c = 0; c < 4; c++) acc[i][j][c] = 0.0f;

    const float* a_base = A  + (size_t)m0 * K;
    const float* b_base = Bt + (size_t)n0 * K;

    // cp.async copy: A tile 256x16 = 1024 f4 (4/thread); B 128x16 = 512 f4 (2/thread)
    auto load_chunk = [&](int c, int buf) {
        #pragma unroll
        for (int j = 0; j < 4; j++) {
            int f = tid + j * 256;            // 0..1023
            int row = f >> 2, slot = f & 3;
            uint32_t saddr = smb + (buf * A_FLOATS + row * 16 + slot * 4) * 4;
            const float* g = a_base + (size_t)row * K + c * 16 + slot * 4;
            asm volatile("cp.async.cg.shared.global [%0], [%1], 16;"
                         :: "r"(saddr), "l"(g) : "memory");
        }
        #pragma unroll
        for (int j = 0; j < 2; j++) {
            int f = tid + j * 256;            // 0..511
            int row = f >> 2, slot = f & 3;
            uint32_t saddr = smb + (2 * A_FLOATS + buf * B_FLOATS + row * 16 + slot * 4) * 4;
            const float* g = b_base + (size_t)row * K + c * 16 + slot * 4;
            asm volatile("cp.async.cg.shared.global [%0], [%1], 16;"
                         :: "r"(saddr), "l"(g) : "memory");
        }
        asm volatile("cp.async.commit_group;" ::: "memory");
    };

    auto compute = [&](int buf) {
        const float* Ab = sm + buf * A_FLOATS;
        const float* Bb = sm + 2 * A_FLOATS + buf * B_FLOATS;
        float4 af0[4], af1[4];
        #pragma unroll
        for (int mt = 0; mt < 4; mt++) {
            int r0 = wm * 64 + mt * 16 + gq;
            af0[mt] = *reinterpret_cast<const float4*>(Ab + r0 * 16 + tig * 4);
            af1[mt] = *reinterpret_cast<const float4*>(Ab + (r0 + 8) * 16 + tig * 4);
        }
        #pragma unroll
        for (int half = 0; half < 2; half++) {
            float4 bf[4];
            #pragma unroll
            for (int q = 0; q < 4; q++) {
                int ncol = wn * 64 + (half * 4 + q) * 8 + gq;
                bf[q] = *reinterpret_cast<const float4*>(Bb + ncol * 16 + tig * 4);
            }
            #pragma unroll
            for (int mt = 0; mt < 4; mt++) {
                #pragma unroll
                for (int q = 0; q < 4; q++) {
                    int nt = half * 4 + q;
                    // float4 components hold logical k = {tig, tig+4, tig+8, tig+12}
                    mma_tf32(acc[mt][nt][0], acc[mt][nt][1], acc[mt][nt][2], acc[mt][nt][3],
                             af0[mt].x, af1[mt].x, af0[mt].y, af1[mt].y,
                             bf[q].x, bf[q].y);
                    mma_tf32(acc[mt][nt][0], acc[mt][nt][1], acc[mt][nt][2], acc[mt][nt][3],
                             af0[mt].z, af1[mt].z, af0[mt].w, af1[mt].w,
                             bf[q].z, bf[q].w);
                }
            }
        }
    };

    int nc = K >> 4;
    load_chunk(0, 0);
    for (int c = 0; c < nc; c++) {
        int buf = c & 1;
        if (c + 1 < nc) {
            load_chunk(c + 1, buf ^ 1);
            asm volatile("cp.async.wait_group 1;" ::: "memory");
        } else {
            asm volatile("cp.async.wait_group 0;" ::: "memory");
        }
        __syncthreads();
        compute(buf);
        __syncthreads();
    }

    // ---------------- epilogues ----------------
    #pragma unroll
    for (int mt = 0; mt < 4; mt++) {
        #pragma unroll
        for (int hh = 0; hh < 2; hh++) {
            int row = m0 + wm * 64 + mt * 16 + gq + hh * 8;
            if (MODE == MODE_QKV) {
                int bb = row / 3136;
                int l  = row - bb * 3136;
                int hr = l / 56;
                int wc = l - hr * 56;
                int gwin = bb * NWIN + (hr / WS) * 8 + (wc / WS);
                int n  = (hr % WS) * WS + (wc % WS);
                size_t ob = (size_t)gwin * (NH * NTOK * HD) + (size_t)n * HD;
                #pragma unroll
                for (int nt = 0; nt < 8; nt++) {
                    int col = n0 + wn * 64 + nt * 8 + 2 * tig;
                    float v0 = acc[mt][nt][2 * hh];
                    float v1 = acc[mt][nt][2 * hh + 1];
                    int head = col >> 5, d = col & 31;
                    out[ob + (size_t)head * (NTOK * HD) + d]     = v0 + bias[col];
                    out[ob + (size_t)head * (NTOK * HD) + d + 1] = v1 + bias[col + 1];
                }
            } else {
                size_t ro = (size_t)row * Ncols;
                #pragma unroll
                for (int nt = 0; nt < 8; nt++) {
                    int col = n0 + wn * 64 + nt * 8 + 2 * tig;
                    float v0 = acc[mt][nt][2 * hh];
                    float v1 = acc[mt][nt][2 * hh + 1];
                    if (MODE == MODE_PROJ) {
                        out[ro + col]     = v0 + bias[col]     + resid[ro + col];
                        out[ro + col + 1] = v1 + bias[col + 1] + resid[ro + col + 1];
                    } else if (MODE == MODE_FC1) {
                        // output feeds FC2 GEMM: write k-permuted + rounded
                        float a0 = v0 + bias[col];
                        float a1 = v1 + bias[col + 1];
                        out[ro + KPERM(col)]     = f2tf32(0.5f * a0 * (1.0f + erff(a0 * 0.70710678118654752f)));
                        out[ro + KPERM(col + 1)] = f2tf32(0.5f * a1 * (1.0f + erff(a1 * 0.70710678118654752f)));
                    } else { // FC2
                        out[ro + col]     = resid[ro + col]     + v0 + bias[col];
                        out[ro + col + 1] = resid[ro + col + 1] + v1 + bias[col + 1];
                    }
                }
            }
        }
    }
}

// ---------------- attention: writes PROJ's A (permuted + rounded) --------
__global__ void __launch_bounds__(128) attn_kernel(
    const float* __restrict__ q, const float* __restrict__ k,
    const float* __restrict__ v, const float* __restrict__ rb,
    float* __restrict__ out)
{
    __shared__ float qs[NTOK * 33];
    __shared__ float ks[NTOK * 33];
    __shared__ float vs[NTOK * 33];
    __shared__ float S[NTOK * NTOK];

    int head = blockIdx.x;
    int g    = blockIdx.y;
    int tid  = threadIdx.x;
    size_t base = ((size_t)g * NH + head) * (NTOK * HD);

    for (int i = tid; i < NTOK * HD; i += 128) {
        int n = i >> 5, d = i & 31;
        qs[n * 33 + d] = q[base + i];
        ks[n * 33 + d] = k[base + i];
        vs[n * 33 + d] = v[base + i];
    }
    __syncthreads();

    const float* rbh = rb + (size_t)head * NTOK * NTOK;
    for (int idx = tid; idx < NTOK * NTOK; idx += 128) {
        int n = idx / NTOK, m = idx - n * NTOK;
        float acc = 0.0f;
        #pragma unroll
        for (int d = 0; d < HD; d++)
            acc = fmaf(qs[n * 33 + d], ks[m * 33 + d], acc);
        S[idx] = acc * SCALE_F + rbh[idx];
    }
    __syncthreads();

    if (tid < NTOK) {
        float mx = -1e30f;
        #pragma unroll 7
        for (int m = 0; m < NTOK; m++) mx = fmaxf(mx, S[tid * NTOK + m]);
        float sum = 0.0f;
        #pragma unroll 7
        for (int m = 0; m < NTOK; m++) {
            float e = __expf(S[tid * NTOK + m] - mx);
            S[tid * NTOK + m] = e;
            sum += e;
        }
        float r = 1.0f / sum;
        #pragma unroll 7
        for (int m = 0; m < NTOK; m++) S[tid * NTOK + m] *= r;
    }
    __syncthreads();

    int bb = g >> 6;
    int wi = g & 63;
    int hr0 = (wi >> 3) * WS, wc0 = (wi & 7) * WS;
    for (int idx = tid; idx < NTOK * HD; idx += 128) {
        int n = idx >> 5, d = idx & 31;
        float acc = 0.0f;
        #pragma unroll 7
        for (int m = 0; m < NTOK; m++)
            acc = fmaf(S[n * NTOK + m], vs[m * 33 + d], acc);
        int hr = hr0 + n / WS, wc = wc0 + n % WS;
        size_t t = (size_t)bb * 3136 + (size_t)hr * 56 + wc;
        int chan = head * HD + d;
        out[t * C_DIM + KPERM(chan)] = f2tf32(acc);
    }
}

// ---------------- launch ----------------
extern "C" void kernel_launch(void* const* d_in, const int* in_sizes, int n_in,
                              void* d_out, int out_size)
{
    const float* x    = (const float*)d_in[0];
    const float* Wq   = (const float*)d_in[1];
    const float* bq   = (const float*)d_in[2];
    const float* Wk   = (const float*)d_in[3];
    const float* bk   = (const float*)d_in[4];
    const float* Wv   = (const float*)d_in[5];
    const float* bv   = (const float*)d_in[6];
    const float* Wp   = (const float*)d_in[7];
    const float* bp   = (const float*)d_in[8];
    const float* rbias= (const float*)d_in[9];
    const float* g1   = (const float*)d_in[10];
    const float* b1   = (const float*)d_in[11];
    const float* g2   = (const float*)d_in[12];
    const float* b2   = (const float*)d_in[13];
    const float* W1   = (const float*)d_in[14];
    const float* bfc1 = (const float*)d_in[15];
    const float* W2   = (const float*)d_in[16];
    const float* bfc2 = (const float*)d_in[17];
    float* out = (float*)d_out;

    float *h, *q, *k, *v, *attn, *act;
    float *wq, *wk, *wv, *wp, *w1t, *w2t;
    cudaGetSymbolAddress((void**)&h,    g_h);
    cudaGetSymbolAddress((void**)&q,    g_q);
    cudaGetSymbolAddress((void**)&k,    g_k);
    cudaGetSymbolAddress((void**)&v,    g_v);
    cudaGetSymbolAddress((void**)&attn, g_attn);
    cudaGetSymbolAddress((void**)&act,  g_act);
    cudaGetSymbolAddress((void**)&wq,   g_wq);
    cudaGetSymbolAddress((void**)&wk,   g_wk);
    cudaGetSymbolAddress((void**)&wv,   g_wv);
    cudaGetSymbolAddress((void**)&wp,   g_wp);
    cudaGetSymbolAddress((void**)&w1t,  g_w1t);
    cudaGetSymbolAddress((void**)&w2t,  g_w2t);

    cudaFuncSetAttribute(tgemm_kernel<MODE_QKV>,  cudaFuncAttributeMaxDynamicSharedMemorySize, SMEM_GEMM_BYTES);
    cudaFuncSetAttribute(tgemm_kernel<MODE_PROJ>, cudaFuncAttributeMaxDynamicSharedMemorySize, SMEM_GEMM_BYTES);
    cudaFuncSetAttribute(tgemm_kernel<MODE_FC1>,  cudaFuncAttributeMaxDynamicSharedMemorySize, SMEM_GEMM_BYTES);
    cudaFuncSetAttribute(tgemm_kernel<MODE_FC2>,  cudaFuncAttributeMaxDynamicSharedMemorySize, SMEM_GEMM_BYTES);

    dim3 g512(4, M_TOK / BMT);      // N=512
    dim3 g2048(16, M_TOK / BMT);    // N=2048
    dim3 attn_grid(NH, B_SZ * NWIN);

    // weight transposes (tf32-rounded, k-permuted)
    transpose_kernel<<<dim3(16, 16), 256>>>(Wq, wq, C_DIM, C_DIM);
    transpose_kernel<<<dim3(16, 16), 256>>>(Wk, wk, C_DIM, C_DIM);
    transpose_kernel<<<dim3(16, 16), 256>>>(Wv, wv, C_DIM, C_DIM);
    transpose_kernel<<<dim3(16, 16), 256>>>(Wp, wp, C_DIM, C_DIM);
    transpose_kernel<<<dim3(64, 16), 256>>>(W1, w1t, C_DIM, HID);
    transpose_kernel<<<dim3(16, 64), 256>>>(W2, w2t, HID, C_DIM);

    ln_kernel<<<M_TOK, 128>>>(x, g1, b1, h);
    tgemm_kernel<MODE_QKV><<<g512, 256, SMEM_GEMM_BYTES>>>(h, wq, bq, nullptr, q, C_DIM, C_DIM);
    tgemm_kernel<MODE_QKV><<<g512, 256, SMEM_GEMM_BYTES>>>(h, wk, bk, nullptr, k, C_DIM, C_DIM);
    tgemm_kernel<MODE_QKV><<<g512, 256, SMEM_GEMM_BYTES>>>(h, wv, bv, nullptr, v, C_DIM, C_DIM);
    attn_kernel<<<attn_grid, 128>>>(q, k, v, rbias, attn);
    tgemm_kernel<MODE_PROJ><<<g512, 256, SMEM_GEMM_BYTES>>>(attn, wp, bp, x, out, C_DIM, C_DIM);
    ln_kernel<<<M_TOK, 128>>>(out, g2, b2, h);
    tgemm_kernel<MODE_FC1><<<g2048, 256, SMEM_GEMM_BYTES>>>(h, w1t, bfc1, nullptr, act, C_DIM, HID);
    tgemm_kernel<MODE_FC2><<<g512, 256, SMEM_GEMM_BYTES>>>(act, w2t, bfc2, out, out, HID, C_DIM);
}

// round 14
// speedup vs baseline: 1.6152x; 1.0552x over previous
#include <cuda_runtime.h>
#include <math.h>
#include <stdint.h>

// ---------------- problem constants ----------------
#define B_SZ   16
#define C_DIM  512
#define WS     7
#define NH     16
#define HD     32
#define HID    2048
#define NTOK   49
#define NWIN   64
#define M_TOK  50176
#define SCALE_F 0.17677669529663687f

// k-permutation within each 16-block: value for logical k stored at
// position p(k) = 4*(k&3) + ((k>>2)&3).  Applied identically to A-cols and
// B-cols by all producers, so GEMM fragment float4 loads are contiguous.
#define KPERM(c) (((c) & ~15) + 4 * ((c) & 3) + (((c) >> 2) & 3))

// ---------------- scratch (device globals; no allocation) ----------------
__device__ float g_h[25690112];
__device__ float g_q[25690112];
__device__ float g_k[25690112];
__device__ float g_v[25690112];
__device__ float g_attn[25690112];
__device__ float g_act[102760448];
__device__ float g_wq[262144], g_wk[262144], g_wv[262144], g_wp[262144];
__device__ float g_w1t[1048576];   // [2048][512]
__device__ float g_w2t[1048576];   // [512][2048]

__device__ __forceinline__ float f2tf32(float f) {
    unsigned r;
    asm("cvt.rna.tf32.f32 %0, %1;" : "=r"(r) : "f"(f));
    return __uint_as_float(r);
}

// ---------------- LayerNorm: tf32-rounded, k-permuted output -------------
__global__ void __launch_bounds__(128) ln_kernel(
    const float* __restrict__ x, const float* __restrict__ gw,
    const float* __restrict__ bw, float* __restrict__ out)
{
    __shared__ float red[8];
    int row = blockIdx.x;
    int tid = threadIdx.x;
    const float4* xr = reinterpret_cast<const float4*>(x + (size_t)row * C_DIM);
    float4 v = xr[tid];
    float s  = v.x + v.y + v.z + v.w;
    float ss = v.x*v.x + v.y*v.y + v.z*v.z + v.w*v.w;
    #pragma unroll
    for (int o = 16; o > 0; o >>= 1) {
        s  += __shfl_xor_sync(0xFFFFFFFFu, s,  o);
        ss += __shfl_xor_sync(0xFFFFFFFFu, ss, o);
    }
    int warp = tid >> 5;
    if ((tid & 31) == 0) { red[warp] = s; red[4 + warp] = ss; }
    __syncthreads();
    float st  = red[0] + red[1] + red[2] + red[3];
    float sst = red[4] + red[5] + red[6] + red[7];
    float mu  = st * (1.0f / C_DIM);
    float var = sst * (1.0f / C_DIM) - mu * mu;
    float inv = rsqrtf(var + 1e-5f);
    float4 gv = reinterpret_cast<const float4*>(gw)[tid];
    float4 bv = reinterpret_cast<const float4*>(bw)[tid];
    float o[4];
    o[0] = f2tf32((v.x - mu) * inv * gv.x + bv.x);
    o[1] = f2tf32((v.y - mu) * inv * gv.y + bv.y);
    o[2] = f2tf32((v.z - mu) * inv * gv.z + bv.z);
    o[3] = f2tf32((v.w - mu) * inv * gv.w + bv.w);
    int c0 = tid * 4;
    int base = c0 & ~15;
    int j = (c0 >> 2) & 3;
    float* orow = out + (size_t)row * C_DIM + base + j;
    #pragma unroll
    for (int e = 0; e < 4; e++) orow[4 * e] = o[e];
}

// ---------------- transpose W (K x N) -> Wt (N x K), permuted+rounded ----
__global__ void __launch_bounds__(256) transpose_kernel(
    const float* __restrict__ src, float* __restrict__ dst, int R, int C)
{
    __shared__ float t[32][33];
    int bx = blockIdx.x * 32, by = blockIdx.y * 32;
    int tx = threadIdx.x & 31;
    int ty4 = (threadIdx.x >> 5) * 4;
    #pragma unroll
    for (int i = 0; i < 4; i++)
        t[ty4 + i][tx] = src[(size_t)(by + ty4 + i) * C + bx + tx];
    __syncthreads();
    #pragma unroll
    for (int i = 0; i < 4; i++) {
        int kk = by + tx;
        dst[(size_t)(bx + ty4 + i) * R + KPERM(kk)] = f2tf32(t[tx][ty4 + i]);
    }
}

// ---------------- tf32 mma GEMM: 256x128 block, BK=32, 3-stage -----------
#define BMT 256
#define BNT 128
#define BKC 32                 // k per chunk

#define MODE_QKV  0
#define MODE_PROJ 1
#define MODE_FC1  2
#define MODE_FC2  3

#define A_FLOATS (BMT * BKC)   // 8192 per stage
#define B_FLOATS (BNT * BKC)   // 4096 per stage
#define STAGE_FLOATS (A_FLOATS + B_FLOATS)      // 12288
#define SMEM_GEMM_BYTES (3 * STAGE_FLOATS * 4)  // 147456

__device__ __forceinline__ uint32_t smem_u32(const void* p) {
    uint32_t a;
    asm("{ .reg .u64 t; cvta.to.shared.u64 t, %1; cvt.u32.u64 %0, t; }"
        : "=r"(a) : "l"(p));
    return a;
}

__device__ __forceinline__ void mma_tf32(
    float& c0, float& c1, float& c2, float& c3,
    float a0, float a1, float a2, float a3,
    float b0, float b1)
{
    asm volatile(
        "mma.sync.aligned.m16n8k8.row.col.f32.tf32.tf32.f32 "
        "{%0,%1,%2,%3}, {%4,%5,%6,%7}, {%8,%9}, {%0,%1,%2,%3};"
        : "+f"(c0), "+f"(c1), "+f"(c2), "+f"(c3)
        : "r"(__float_as_uint(a0)), "r"(__float_as_uint(a1)),
          "r"(__float_as_uint(a2)), "r"(__float_as_uint(a3)),
          "r"(__float_as_uint(b0)), "r"(__float_as_uint(b1)));
}

template<int MODE>
__global__ void __launch_bounds__(256) tgemm_kernel(
    const float* __restrict__ A,      // M x K (tf32-rounded, k-permuted)
    const float* __restrict__ Bt,     // Ncols x K (tf32-rounded, k-permuted)
    const float* __restrict__ bias,
    const float* __restrict__ resid,
    float* __restrict__ out,
    int K, int Ncols)
{
    extern __shared__ float sm[];
    uint32_t smb = smem_u32(sm);

    int tid  = threadIdx.x;
    int lane = tid & 31;
    int warp = tid >> 5;
    int gq   = lane >> 2;     // 0..7
    int tig  = lane & 3;      // 0..3
    int wm   = warp >> 1;     // 0..3 (64 rows each)
    int wn   = warp & 1;      // 0..1 (64 cols each)
    int m0 = blockIdx.y * BMT;
    int n0 = blockIdx.x * BNT;

    float acc[4][8][4];
    #pragma unroll
    for (int i = 0; i < 4; i++)
        #pragma unroll
        for (int j = 0; j < 8; j++)
            #pragma unroll
            for (int c = 0; c < 4; c++) acc[i][j][c] = 0.0f;

    const float* a_base = A  + (size_t)m0 * K;
    const float* b_base = Bt + (size_t)n0 * K;

    // per chunk: A 256x32 = 2048 f4 (8/thr); B 128x32 = 1024 f4 (4/thr)
    auto load_chunk = [&](int c, int stage) {
        uint32_t sbase = smb + stage * (STAGE_FLOATS * 4);
        #pragma unroll
        for (int j = 0; j < 8; j++) {
            int f = tid + j * 256;            // 0..2047
            int row = f >> 3, slot = f & 7;
            uint32_t saddr = sbase + (row * BKC + slot * 4) * 4;
            const float* g = a_base + (size_t)row * K + c * BKC + slot * 4;
            asm volatile("cp.async.cg.shared.global [%0], [%1], 16;"
                         :: "r"(saddr), "l"(g) : "memory");
        }
        #pragma unroll
        for (int j = 0; j < 4; j++) {
            int f = tid + j * 256;            // 0..1023
            int row = f >> 3, slot = f & 7;
            uint32_t saddr = sbase + (A_FLOATS + row * BKC + slot * 4) * 4;
            const float* g = b_base + (size_t)row * K + c * BKC + slot * 4;
            asm volatile("cp.async.cg.shared.global [%0], [%1], 16;"
                         :: "r"(saddr), "l"(g) : "memory");
        }
        asm volatile("cp.async.commit_group;" ::: "memory");
    };

    auto compute = [&](int stage) {
        const float* Ab = sm + stage * STAGE_FLOATS;
        const float* Bb = Ab + A_FLOATS;
        #pragma unroll
        for (int kh = 0; kh < 2; kh++) {          // two 16-k sub-chunks
            int ko = kh * 16 + tig * 4;
            float4 af0[4], af1[4];
            #pragma unroll
            for (int mt = 0; mt < 4; mt++) {
                int r0 = wm * 64 + mt * 16 + gq;
                af0[mt] = *reinterpret_cast<const float4*>(Ab + r0 * BKC + ko);
                af1[mt] = *reinterpret_cast<const float4*>(Ab + (r0 + 8) * BKC + ko);
            }
            #pragma unroll
            for (int half = 0; half < 2; half++) {
                float4 bf[4];
                #pragma unroll
                for (int q = 0; q < 4; q++) {
                    int ncol = wn * 64 + (half * 4 + q) * 8 + gq;
                    bf[q] = *reinterpret_cast<const float4*>(Bb + ncol * BKC + ko);
                }
                #pragma unroll
                for (int mt = 0; mt < 4; mt++) {
                    #pragma unroll
                    for (int q = 0; q < 4; q++) {
                        int nt = half * 4 + q;
                        mma_tf32(acc[mt][nt][0], acc[mt][nt][1], acc[mt][nt][2], acc[mt][nt][3],
                                 af0[mt].x, af1[mt].x, af0[mt].y, af1[mt].y,
                                 bf[q].x, bf[q].y);
                        mma_tf32(acc[mt][nt][0], acc[mt][nt][1], acc[mt][nt][2], acc[mt][nt][3],
                                 af0[mt].z, af1[mt].z, af0[mt].w, af1[mt].w,
                                 bf[q].z, bf[q].w);
                    }
                }
            }
        }
    };

    int nc = K / BKC;                  // >= 2 always (K=512 -> 16)
    load_chunk(0, 0);
    load_chunk(1, 1);
    for (int c = 0; c < nc; c++) {
        int stage = c % 3;
        if (c + 1 < nc) asm volatile("cp.async.wait_group 1;" ::: "memory");
        else            asm volatile("cp.async.wait_group 0;" ::: "memory");
        __syncthreads();               // chunk c visible; all warps done with stage (c-1)%3
        if (c + 2 < nc) load_chunk(c + 2, (c + 2) % 3);
        compute(stage);
    }

    // ---------------- epilogues ----------------
    #pragma unroll
    for (int mt = 0; mt < 4; mt++) {
        #pragma unroll
        for (int hh = 0; hh < 2; hh++) {
            int row = m0 + wm * 64 + mt * 16 + gq + hh * 8;
            if (MODE == MODE_QKV) {
                int bb = row / 3136;
                int l  = row - bb * 3136;
                int hr = l / 56;
                int wc = l - hr * 56;
                int gwin = bb * NWIN + (hr / WS) * 8 + (wc / WS);
                int n  = (hr % WS) * WS + (wc % WS);
                size_t ob = (size_t)gwin * (NH * NTOK * HD) + (size_t)n * HD;
                #pragma unroll
                for (int nt = 0; nt < 8; nt++) {
                    int col = n0 + wn * 64 + nt * 8 + 2 * tig;
                    float v0 = acc[mt][nt][2 * hh];
                    float v1 = acc[mt][nt][2 * hh + 1];
                    int head = col >> 5, d = col & 31;
                    out[ob + (size_t)head * (NTOK * HD) + d]     = v0 + bias[col];
                    out[ob + (size_t)head * (NTOK * HD) + d + 1] = v1 + bias[col + 1];
                }
            } else {
                size_t ro = (size_t)row * Ncols;
                #pragma unroll
                for (int nt = 0; nt < 8; nt++) {
                    int col = n0 + wn * 64 + nt * 8 + 2 * tig;
                    float v0 = acc[mt][nt][2 * hh];
                    float v1 = acc[mt][nt][2 * hh + 1];
                    if (MODE == MODE_PROJ) {
                        out[ro + col]     = v0 + bias[col]     + resid[ro + col];
                        out[ro + col + 1] = v1 + bias[col + 1] + resid[ro + col + 1];
                    } else if (MODE == MODE_FC1) {
                        float a0 = v0 + bias[col];
                        float a1 = v1 + bias[col + 1];
                        out[ro + KPERM(col)]     = f2tf32(0.5f * a0 * (1.0f + erff(a0 * 0.70710678118654752f)));
                        out[ro + KPERM(col + 1)] = f2tf32(0.5f * a1 * (1.0f + erff(a1 * 0.70710678118654752f)));
                    } else { // FC2
                        out[ro + col]     = resid[ro + col]     + v0 + bias[col];
                        out[ro + col + 1] = resid[ro + col + 1] + v1 + bias[col + 1];
                    }
                }
            }
        }
    }
}

// ---------------- attention: writes PROJ's A (permuted + rounded) --------
__global__ void __launch_bounds__(128) attn_kernel(
    const float* __restrict__ q, const float* __restrict__ k,
    const float* __restrict__ v, const float* __restrict__ rb,
    float* __restrict__ out)
{
    __shared__ float qs[NTOK * 33];
    __shared__ float ks[NTOK * 33];
    __shared__ float vs[NTOK * 33];
    __shared__ float S[NTOK * NTOK];

    int head = blockIdx.x;
    int g    = blockIdx.y;
    int tid  = threadIdx.x;
    size_t base = ((size_t)g * NH + head) * (NTOK * HD);

    for (int i = tid; i < NTOK * HD; i += 128) {
        int n = i >> 5, d = i & 31;
        qs[n * 33 + d] = q[base + i];
        ks[n * 33 + d] = k[base + i];
        vs[n * 33 + d] = v[base + i];
    }
    __syncthreads();

    const float* rbh = rb + (size_t)head * NTOK * NTOK;
    for (int idx = tid; idx < NTOK * NTOK; idx += 128) {
        int n = idx / NTOK, m = idx - n * NTOK;
        float acc = 0.0f;
        #pragma unroll
        for (int d = 0; d < HD; d++)
            acc = fmaf(qs[n * 33 + d], ks[m * 33 + d], acc);
        S[idx] = acc * SCALE_F + rbh[idx];
    }
    __syncthreads();

    if (tid < NTOK) {
        float mx = -1e30f;
        #pragma unroll 7
        for (int m = 0; m < NTOK; m++) mx = fmaxf(mx, S[tid * NTOK + m]);
        float sum = 0.0f;
        #pragma unroll 7
        for (int m = 0; m < NTOK; m++) {
            float e = __expf(S[tid * NTOK + m] - mx);
            S[tid * NTOK + m] = e;
            sum += e;
        }
        float r = 1.0f / sum;
        #pragma unroll 7
        for (int m = 0; m < NTOK; m++) S[tid * NTOK + m] *= r;
    }
    __syncthreads();

    int bb = g >> 6;
    int wi = g & 63;
    int hr0 = (wi >> 3) * WS, wc0 = (wi & 7) * WS;
    for (int idx = tid; idx < NTOK * HD; idx += 128) {
        int n = idx >> 5, d = idx & 31;
        float acc = 0.0f;
        #pragma unroll 7
        for (int m = 0; m < NTOK; m++)
            acc = fmaf(S[n * NTOK + m], vs[m * 33 + d], acc);
        int hr = hr0 + n / WS, wc = wc0 + n % WS;
        size_t t = (size_t)bb * 3136 + (size_t)hr * 56 + wc;
        int chan = head * HD + d;
        out[t * C_DIM + KPERM(chan)] = f2tf32(acc);
    }
}

// ---------------- launch ----------------
extern "C" void kernel_launch(void* const* d_in, const int* in_sizes, int n_in,
                              void* d_out, int out_size)
{
    const float* x    = (const float*)d_in[0];
    const float* Wq   = (const float*)d_in[1];
    const float* bq   = (const float*)d_in[2];
    const float* Wk   = (const float*)d_in[3];
    const float* bk   = (const float*)d_in[4];
    const float* Wv   = (const float*)d_in[5];
    const float* bv   = (const float*)d_in[6];
    const float* Wp   = (const float*)d_in[7];
    const float* bp   = (const float*)d_in[8];
    const float* rbias= (const float*)d_in[9];
    const float* g1   = (const float*)d_in[10];
    const float* b1   = (const float*)d_in[11];
    const float* g2   = (const float*)d_in[12];
    const float* b2   = (const float*)d_in[13];
    const float* W1   = (const float*)d_in[14];
    const float* bfc1 = (const float*)d_in[15];
    const float* W2   = (const float*)d_in[16];
    const float* bfc2 = (const float*)d_in[17];
    float* out = (float*)d_out;

    float *h, *q, *k, *v, *attn, *act;
    float *wq, *wk, *wv, *wp, *w1t, *w2t;
    cudaGetSymbolAddress((void**)&h,    g_h);
    cudaGetSymbolAddress((void**)&q,    g_q);
    cudaGetSymbolAddress((void**)&k,    g_k);
    cudaGetSymbolAddress((void**)&v,    g_v);
    cudaGetSymbolAddress((void**)&attn, g_attn);
    cudaGetSymbolAddress((void**)&act,  g_act);
    cudaGetSymbolAddress((void**)&wq,   g_wq);
    cudaGetSymbolAddress((void**)&wk,   g_wk);
    cudaGetSymbolAddress((void**)&wv,   g_wv);
    cudaGetSymbolAddress((void**)&wp,   g_wp);
    cudaGetSymbolAddress((void**)&w1t,  g_w1t);
    cudaGetSymbolAddress((void**)&w2t,  g_w2t);

    cudaFuncSetAttribute(tgemm_kernel<MODE_QKV>,  cudaFuncAttributeMaxDynamicSharedMemorySize, SMEM_GEMM_BYTES);
    cudaFuncSetAttribute(tgemm_kernel<MODE_PROJ>, cudaFuncAttributeMaxDynamicSharedMemorySize, SMEM_GEMM_BYTES);
    cudaFuncSetAttribute(tgemm_kernel<MODE_FC1>,  cudaFuncAttributeMaxDynamicSharedMemorySize, SMEM_GEMM_BYTES);
    cudaFuncSetAttribute(tgemm_kernel<MODE_FC2>,  cudaFuncAttributeMaxDynamicSharedMemorySize, SMEM_GEMM_BYTES);

    dim3 g512(4, M_TOK / BMT);      // N=512
    dim3 g2048(16, M_TOK / BMT);    // N=2048
    dim3 attn_grid(NH, B_SZ * NWIN);

    transpose_kernel<<<dim3(16, 16), 256>>>(Wq, wq, C_DIM, C_DIM);
    transpose_kernel<<<dim3(16, 16), 256>>>(Wk, wk, C_DIM, C_DIM);
    transpose_kernel<<<dim3(16, 16), 256>>>(Wv, wv, C_DIM, C_DIM);
    transpose_kernel<<<dim3(16, 16), 256>>>(Wp, wp, C_DIM, C_DIM);
    transpose_kernel<<<dim3(64, 16), 256>>>(W1, w1t, C_DIM, HID);
    transpose_kernel<<<dim3(16, 64), 256>>>(W2, w2t, HID, C_DIM);

    ln_kernel<<<M_TOK, 128>>>(x, g1, b1, h);
    tgemm_kernel<MODE_QKV><<<g512, 256, SMEM_GEMM_BYTES>>>(h, wq, bq, nullptr, q, C_DIM, C_DIM);
    tgemm_kernel<MODE_QKV><<<g512, 256, SMEM_GEMM_BYTES>>>(h, wk, bk, nullptr, k, C_DIM, C_DIM);
    tgemm_kernel<MODE_QKV><<<g512, 256, SMEM_GEMM_BYTES>>>(h, wv, bv, nullptr, v, C_DIM, C_DIM);
    attn_kernel<<<attn_grid, 128>>>(q, k, v, rbias, attn);
    tgemm_kernel<MODE_PROJ><<<g512, 256, SMEM_GEMM_BYTES>>>(attn, wp, bp, x, out, C_DIM, C_DIM);
    ln_kernel<<<M_TOK, 128>>>(out, g2, b2, h);
    tgemm_kernel<MODE_FC1><<<g2048, 256, SMEM_GEMM_BYTES>>>(h, w1t, bfc1, nullptr, act, C_DIM, HID);
    tgemm_kernel<MODE_FC2><<<g512, 256, SMEM_GEMM_BYTES>>>(act, w2t, bfc2, out, out, HID, C_DIM);
}

// round 15
// speedup vs baseline: 1.6260x; 1.0066x over previous
#include <cuda_runtime.h>
#include <math.h>
#include <stdint.h>

// ---------------- problem constants ----------------
#define B_SZ   16
#define C_DIM  512
#define WS     7
#define NH     16
#define HD     32
#define HID    2048
#define NTOK   49
#define NWIN   64
#define M_TOK  50176
#define SCALE_F 0.17677669529663687f

// k-permutation within each 16-block: value for logical k stored at
// position p(k) = 4*(k&3) + ((k>>2)&3).  Applied identically to A-cols and
// B-cols by all producers, so GEMM fragment float4 loads are contiguous.
#define KPERM(c) (((c) & ~15) + 4 * ((c) & 3) + (((c) >> 2) & 3))

// ---------------- scratch (device globals; no allocation) ----------------
__device__ float g_h[25690112];
__device__ float g_q[25690112];
__device__ float g_k[25690112];
__device__ float g_v[25690112];
__device__ float g_attn[25690112];
__device__ float g_act[102760448];
__device__ float g_wq[262144], g_wk[262144], g_wv[262144], g_wp[262144];
__device__ float g_w1t[1048576];   // [2048][512]
__device__ float g_w2t[1048576];   // [512][2048]

__device__ __forceinline__ float f2tf32(float f) {
    unsigned r;
    asm("cvt.rna.tf32.f32 %0, %1;" : "=r"(r) : "f"(f));
    return __uint_as_float(r);
}

// ---------------- LayerNorm: tf32-rounded, k-permuted output -------------
__global__ void __launch_bounds__(128) ln_kernel(
    const float* __restrict__ x, const float* __restrict__ gw,
    const float* __restrict__ bw, float* __restrict__ out)
{
    __shared__ float red[8];
    int row = blockIdx.x;
    int tid = threadIdx.x;
    const float4* xr = reinterpret_cast<const float4*>(x + (size_t)row * C_DIM);
    float4 v = xr[tid];
    float s  = v.x + v.y + v.z + v.w;
    float ss = v.x*v.x + v.y*v.y + v.z*v.z + v.w*v.w;
    #pragma unroll
    for (int o = 16; o > 0; o >>= 1) {
        s  += __shfl_xor_sync(0xFFFFFFFFu, s,  o);
        ss += __shfl_xor_sync(0xFFFFFFFFu, ss, o);
    }
    int warp = tid >> 5;
    if ((tid & 31) == 0) { red[warp] = s; red[4 + warp] = ss; }
    __syncthreads();
    float st  = red[0] + red[1] + red[2] + red[3];
    float sst = red[4] + red[5] + red[6] + red[7];
    float mu  = st * (1.0f / C_DIM);
    float var = sst * (1.0f / C_DIM) - mu * mu;
    float inv = rsqrtf(var + 1e-5f);
    float4 gv = reinterpret_cast<const float4*>(gw)[tid];
    float4 bv = reinterpret_cast<const float4*>(bw)[tid];
    float o[4];
    o[0] = f2tf32((v.x - mu) * inv * gv.x + bv.x);
    o[1] = f2tf32((v.y - mu) * inv * gv.y + bv.y);
    o[2] = f2tf32((v.z - mu) * inv * gv.z + bv.z);
    o[3] = f2tf32((v.w - mu) * inv * gv.w + bv.w);
    int c0 = tid * 4;
    int base = c0 & ~15;
    int j = (c0 >> 2) & 3;
    float* orow = out + (size_t)row * C_DIM + base + j;
    #pragma unroll
    for (int e = 0; e < 4; e++) orow[4 * e] = o[e];
}

// ---------------- transpose W (K x N) -> Wt (N x K), permuted+rounded ----
__global__ void __launch_bounds__(256) transpose_kernel(
    const float* __restrict__ src, float* __restrict__ dst, int R, int C)
{
    __shared__ float t[32][33];
    int bx = blockIdx.x * 32, by = blockIdx.y * 32;
    int tx = threadIdx.x & 31;
    int ty4 = (threadIdx.x >> 5) * 4;
    #pragma unroll
    for (int i = 0; i < 4; i++)
        t[ty4 + i][tx] = src[(size_t)(by + ty4 + i) * C + bx + tx];
    __syncthreads();
    #pragma unroll
    for (int i = 0; i < 4; i++) {
        int kk = by + tx;
        dst[(size_t)(bx + ty4 + i) * R + KPERM(kk)] = f2tf32(t[tx][ty4 + i]);
    }
}

// ---------------- tf32 mma GEMM: 256x128 block, BK=32, 3-stage -----------
#define BMT 256
#define BNT 128
#define BKC 32                 // k per chunk

#define MODE_QKV  0
#define MODE_PROJ 1
#define MODE_FC1  2
#define MODE_FC2  3

#define A_FLOATS (BMT * BKC)   // 8192 per stage
#define B_FLOATS (BNT * BKC)   // 4096 per stage
#define STAGE_FLOATS (A_FLOATS + B_FLOATS)      // 12288
#define SMEM_GEMM_BYTES (3 * STAGE_FLOATS * 4)  // 147456

__device__ __forceinline__ uint32_t smem_u32(const void* p) {
    uint32_t a;
    asm("{ .reg .u64 t; cvta.to.shared.u64 t, %1; cvt.u32.u64 %0, t; }"
        : "=r"(a) : "l"(p));
    return a;
}

__device__ __forceinline__ void mma_tf32(
    float& c0, float& c1, float& c2, float& c3,
    float a0, float a1, float a2, float a3,
    float b0, float b1)
{
    asm volatile(
        "mma.sync.aligned.m16n8k8.row.col.f32.tf32.tf32.f32 "
        "{%0,%1,%2,%3}, {%4,%5,%6,%7}, {%8,%9}, {%0,%1,%2,%3};"
        : "+f"(c0), "+f"(c1), "+f"(c2), "+f"(c3)
        : "r"(__float_as_uint(a0)), "r"(__float_as_uint(a1)),
          "r"(__float_as_uint(a2)), "r"(__float_as_uint(a3)),
          "r"(__float_as_uint(b0)), "r"(__float_as_uint(b1)));
}

template<int MODE>
__global__ void __launch_bounds__(256) tgemm_kernel(
    const float* __restrict__ A,      // M x K (tf32-rounded, k-permuted)
    const float* __restrict__ Bt,     // Ncols x K (tf32-rounded, k-permuted)
    const float* __restrict__ bias,
    const float* __restrict__ resid,
    float* __restrict__ out,
    int K, int Ncols)
{
    extern __shared__ float sm[];
    uint32_t smb = smem_u32(sm);

    int tid  = threadIdx.x;
    int lane = tid & 31;
    int warp = tid >> 5;
    int gq   = lane >> 2;     // 0..7
    int tig  = lane & 3;      // 0..3
    int wm   = warp >> 1;     // 0..3 (64 rows each)
    int wn   = warp & 1;      // 0..1 (64 cols each)
    int m0 = blockIdx.y * BMT;
    int n0 = blockIdx.x * BNT;

    float acc[4][8][4];
    #pragma unroll
    for (int i = 0; i < 4; i++)
        #pragma unroll
        for (int j = 0; j < 8; j++)
            #pragma unroll
            for (int c = 0; c < 4; c++) acc[i][j][c] = 0.0f;

    const float* a_base = A  + (size_t)m0 * K;
    const float* b_base = Bt + (size_t)n0 * K;

    // per chunk: A 256x32 = 2048 f4 (8/thr); B 128x32 = 1024 f4 (4/thr)
    auto load_chunk = [&](int c, int stage) {
        uint32_t sbase = smb + stage * (STAGE_FLOATS * 4);
        #pragma unroll
        for (int j = 0; j < 8; j++) {
            int f = tid + j * 256;            // 0..2047
            int row = f >> 3, slot = f & 7;
            uint32_t saddr = sbase + (row * BKC + slot * 4) * 4;
            const float* g = a_base + (size_t)row * K + c * BKC + slot * 4;
            asm volatile("cp.async.cg.shared.global [%0], [%1], 16;"
                         :: "r"(saddr), "l"(g) : "memory");
        }
        #pragma unroll
        for (int j = 0; j < 4; j++) {
            int f = tid + j * 256;            // 0..1023
            int row = f >> 3, slot = f & 7;
            uint32_t saddr = sbase + (A_FLOATS + row * BKC + slot * 4) * 4;
            const float* g = b_base + (size_t)row * K + c * BKC + slot * 4;
            asm volatile("cp.async.cg.shared.global [%0], [%1], 16;"
                         :: "r"(saddr), "l"(g) : "memory");
        }
        asm volatile("cp.async.commit_group;" ::: "memory");
    };

    // Dependency-aware MMA schedule: for each (kh, half) issue all 16
    // independent (mt,q) MMAs of k-step 0, then all 16 of k-step 1.
    // Per-accumulator order is unchanged (k0 then k1) => bit-identical
    // results; distance between dependent MMAs grows from 1 to 16.
    auto compute = [&](int stage) {
        const float* Ab = sm + stage * STAGE_FLOATS;
        const float* Bb = Ab + A_FLOATS;
        #pragma unroll
        for (int kh = 0; kh < 2; kh++) {          // two 16-k sub-chunks
            int ko = kh * 16 + tig * 4;
            float4 af0[4], af1[4];
            #pragma unroll
            for (int mt = 0; mt < 4; mt++) {
                int r0 = wm * 64 + mt * 16 + gq;
                af0[mt] = *reinterpret_cast<const float4*>(Ab + r0 * BKC + ko);
                af1[mt] = *reinterpret_cast<const float4*>(Ab + (r0 + 8) * BKC + ko);
            }
            #pragma unroll
            for (int half = 0; half < 2; half++) {
                float4 bf[4];
                #pragma unroll
                for (int q = 0; q < 4; q++) {
                    int ncol = wn * 64 + (half * 4 + q) * 8 + gq;
                    bf[q] = *reinterpret_cast<const float4*>(Bb + ncol * BKC + ko);
                }
                // k-step 0 (components .x/.y) for all 16 accumulators
                #pragma unroll
                for (int mt = 0; mt < 4; mt++)
                    #pragma unroll
                    for (int q = 0; q < 4; q++) {
                        int nt = half * 4 + q;
                        mma_tf32(acc[mt][nt][0], acc[mt][nt][1], acc[mt][nt][2], acc[mt][nt][3],
                                 af0[mt].x, af1[mt].x, af0[mt].y, af1[mt].y,
                                 bf[q].x, bf[q].y);
                    }
                // k-step 1 (components .z/.w) for all 16 accumulators
                #pragma unroll
                for (int mt = 0; mt < 4; mt++)
                    #pragma unroll
                    for (int q = 0; q < 4; q++) {
                        int nt = half * 4 + q;
                        mma_tf32(acc[mt][nt][0], acc[mt][nt][1], acc[mt][nt][2], acc[mt][nt][3],
                                 af0[mt].z, af1[mt].z, af0[mt].w, af1[mt].w,
                                 bf[q].z, bf[q].w);
                    }
            }
        }
    };

    int nc = K / BKC;                  // >= 2 always (K=512 -> 16)
    load_chunk(0, 0);
    load_chunk(1, 1);
    for (int c = 0; c < nc; c++) {
        int stage = c % 3;
        if (c + 1 < nc) asm volatile("cp.async.wait_group 1;" ::: "memory");
        else            asm volatile("cp.async.wait_group 0;" ::: "memory");
        __syncthreads();               // chunk c visible; all warps done with stage (c-1)%3
        if (c + 2 < nc) load_chunk(c + 2, (c + 2) % 3);
        compute(stage);
    }

    // ---------------- epilogues ----------------
    #pragma unroll
    for (int mt = 0; mt < 4; mt++) {
        #pragma unroll
        for (int hh = 0; hh < 2; hh++) {
            int row = m0 + wm * 64 + mt * 16 + gq + hh * 8;
            if (MODE == MODE_QKV) {
                int bb = row / 3136;
                int l  = row - bb * 3136;
                int hr = l / 56;
                int wc = l - hr * 56;
                int gwin = bb * NWIN + (hr / WS) * 8 + (wc / WS);
                int n  = (hr % WS) * WS + (wc % WS);
                size_t ob = (size_t)gwin * (NH * NTOK * HD) + (size_t)n * HD;
                #pragma unroll
                for (int nt = 0; nt < 8; nt++) {
                    int col = n0 + wn * 64 + nt * 8 + 2 * tig;
                    float v0 = acc[mt][nt][2 * hh];
                    float v1 = acc[mt][nt][2 * hh + 1];
                    int head = col >> 5, d = col & 31;
                    out[ob + (size_t)head * (NTOK * HD) + d]     = v0 + bias[col];
                    out[ob + (size_t)head * (NTOK * HD) + d + 1] = v1 + bias[col + 1];
                }
            } else {
                size_t ro = (size_t)row * Ncols;
                #pragma unroll
                for (int nt = 0; nt < 8; nt++) {
                    int col = n0 + wn * 64 + nt * 8 + 2 * tig;
                    float v0 = acc[mt][nt][2 * hh];
                    float v1 = acc[mt][nt][2 * hh + 1];
                    if (MODE == MODE_PROJ) {
                        out[ro + col]     = v0 + bias[col]     + resid[ro + col];
                        out[ro + col + 1] = v1 + bias[col + 1] + resid[ro + col + 1];
                    } else if (MODE == MODE_FC1) {
                        float a0 = v0 + bias[col];
                        float a1 = v1 + bias[col + 1];
                        out[ro + KPERM(col)]     = f2tf32(0.5f * a0 * (1.0f + erff(a0 * 0.70710678118654752f)));
                        out[ro + KPERM(col + 1)] = f2tf32(0.5f * a1 * (1.0f + erff(a1 * 0.70710678118654752f)));
                    } else { // FC2
                        out[ro + col]     = resid[ro + col]     + v0 + bias[col];
                        out[ro + col + 1] = resid[ro + col + 1] + v1 + bias[col + 1];
                    }
                }
            }
        }
    }
}

// ---------------- attention: writes PROJ's A (permuted + rounded) --------
__global__ void __launch_bounds__(128) attn_kernel(
    const float* __restrict__ q, const float* __restrict__ k,
    const float* __restrict__ v, const float* __restrict__ rb,
    float* __restrict__ out)
{
    __shared__ float qs[NTOK * 33];
    __shared__ float ks[NTOK * 33];
    __shared__ float vs[NTOK * 33];
    __shared__ float S[NTOK * NTOK];

    int head = blockIdx.x;
    int g    = blockIdx.y;
    int tid  = threadIdx.x;
    size_t base = ((size_t)g * NH + head) * (NTOK * HD);

    for (int i = tid; i < NTOK * HD; i += 128) {
        int n = i >> 5, d = i & 31;
        qs[n * 33 + d] = q[base + i];
        ks[n * 33 + d] = k[base + i];
        vs[n * 33 + d] = v[base + i];
    }
    __syncthreads();

    const float* rbh = rb + (size_t)head * NTOK * NTOK;
    for (int idx = tid; idx < NTOK * NTOK; idx += 128) {
        int n = idx / NTOK, m = idx - n * NTOK;
        float acc = 0.0f;
        #pragma unroll
        for (int d = 0; d < HD; d++)
            acc = fmaf(qs[n * 33 + d], ks[m * 33 + d], acc);
        S[idx] = acc * SCALE_F + rbh[idx];
    }
    __syncthreads();

    if (tid < NTOK) {
        float mx = -1e30f;
        #pragma unroll 7
        for (int m = 0; m < NTOK; m++) mx = fmaxf(mx, S[tid * NTOK + m]);
        float sum = 0.0f;
        #pragma unroll 7
        for (int m = 0; m < NTOK; m++) {
            float e = __expf(S[tid * NTOK + m] - mx);
            S[tid * NTOK + m] = e;
            sum += e;
        }
        float r = 1.0f / sum;
        #pragma unroll 7
        for (int m = 0; m < NTOK; m++) S[tid * NTOK + m] *= r;
    }
    __syncthreads();

    int bb = g >> 6;
    int wi = g & 63;
    int hr0 = (wi >> 3) * WS, wc0 = (wi & 7) * WS;
    for (int idx = tid; idx < NTOK * HD; idx += 128) {
        int n = idx >> 5, d = idx & 31;
        float acc = 0.0f;
        #pragma unroll 7
        for (int m = 0; m < NTOK; m++)
            acc = fmaf(S[n * NTOK + m], vs[m * 33 + d], acc);
        int hr = hr0 + n / WS, wc = wc0 + n % WS;
        size_t t = (size_t)bb * 3136 + (size_t)hr * 56 + wc;
        int chan = head * HD + d;
        out[t * C_DIM + KPERM(chan)] = f2tf32(acc);
    }
}

// ---------------- launch ----------------
extern "C" void kernel_launch(void* const* d_in, const int* in_sizes, int n_in,
                              void* d_out, int out_size)
{
    const float* x    = (const float*)d_in[0];
    const float* Wq   = (const float*)d_in[1];
    const float* bq   = (const float*)d_in[2];
    const float* Wk   = (const float*)d_in[3];
    const float* bk   = (const float*)d_in[4];
    const float* Wv   = (const float*)d_in[5];
    const float* bv   = (const float*)d_in[6];
    const float* Wp   = (const float*)d_in[7];
    const float* bp   = (const float*)d_in[8];
    const float* rbias= (const float*)d_in[9];
    const float* g1   = (const float*)d_in[10];
    const float* b1   = (const float*)d_in[11];
    const float* g2   = (const float*)d_in[12];
    const float* b2   = (const float*)d_in[13];
    const float* W1   = (const float*)d_in[14];
    const float* bfc1 = (const float*)d_in[15];
    const float* W2   = (const float*)d_in[16];
    const float* bfc2 = (const float*)d_in[17];
    float* out = (float*)d_out;

    float *h, *q, *k, *v, *attn, *act;
    float *wq, *wk, *wv, *wp, *w1t, *w2t;
    cudaGetSymbolAddress((void**)&h,    g_h);
    cudaGetSymbolAddress((void**)&q,    g_q);
    cudaGetSymbolAddress((void**)&k,    g_k);
    cudaGetSymbolAddress((void**)&v,    g_v);
    cudaGetSymbolAddress((void**)&attn, g_attn);
    cudaGetSymbolAddress((void**)&act,  g_act);
    cudaGetSymbolAddress((void**)&wq,   g_wq);
    cudaGetSymbolAddress((void**)&wk,   g_wk);
    cudaGetSymbolAddress((void**)&wv,   g_wv);
    cudaGetSymbolAddress((void**)&wp,   g_wp);
    cudaGetSymbolAddress((void**)&w1t,  g_w1t);
    cudaGetSymbolAddress((void**)&w2t,  g_w2t);

    cudaFuncSetAttribute(tgemm_kernel<MODE_QKV>,  cudaFuncAttributeMaxDynamicSharedMemorySize, SMEM_GEMM_BYTES);
    cudaFuncSetAttribute(tgemm_kernel<MODE_PROJ>, cudaFuncAttributeMaxDynamicSharedMemorySize, SMEM_GEMM_BYTES);
    cudaFuncSetAttribute(tgemm_kernel<MODE_FC1>,  cudaFuncAttributeMaxDynamicSharedMemorySize, SMEM_GEMM_BYTES);
    cudaFuncSetAttribute(tgemm_kernel<MODE_FC2>,  cudaFuncAttributeMaxDynamicSharedMemorySize, SMEM_GEMM_BYTES);

    dim3 g512(4, M_TOK / BMT);      // N=512
    dim3 g2048(16, M_TOK / BMT);    // N=2048
    dim3 attn_grid(NH, B_SZ * NWIN);

    transpose_kernel<<<dim3(16, 16), 256>>>(Wq, wq, C_DIM, C_DIM);
    transpose_kernel<<<dim3(16, 16), 256>>>(Wk, wk, C_DIM, C_DIM);
    transpose_kernel<<<dim3(16, 16), 256>>>(Wv, wv, C_DIM, C_DIM);
    transpose_kernel<<<dim3(16, 16), 256>>>(Wp, wp, C_DIM, C_DIM);
    transpose_kernel<<<dim3(64, 16), 256>>>(W1, w1t, C_DIM, HID);
    transpose_kernel<<<dim3(16, 64), 256>>>(W2, w2t, HID, C_DIM);

    ln_kernel<<<M_TOK, 128>>>(x, g1, b1, h);
    tgemm_kernel<MODE_QKV><<<g512, 256, SMEM_GEMM_BYTES>>>(h, wq, bq, nullptr, q, C_DIM, C_DIM);
    tgemm_kernel<MODE_QKV><<<g512, 256, SMEM_GEMM_BYTES>>>(h, wk, bk, nullptr, k, C_DIM, C_DIM);
    tgemm_kernel<MODE_QKV><<<g512, 256, SMEM_GEMM_BYTES>>>(h, wv, bv, nullptr, v, C_DIM, C_DIM);
    attn_kernel<<<attn_grid, 128>>>(q, k, v, rbias, attn);
    tgemm_kernel<MODE_PROJ><<<g512, 256, SMEM_GEMM_BYTES>>>(attn, wp, bp, x, out, C_DIM, C_DIM);
    ln_kernel<<<M_TOK, 128>>>(out, g2, b2, h);
    tgemm_kernel<MODE_FC1><<<g2048, 256, SMEM_GEMM_BYTES>>>(h, w1t, bfc1, nullptr, act, C_DIM, HID);
    tgemm_kernel<MODE_FC2><<<g512, 256, SMEM_GEMM_BYTES>>>(act, w2t, bfc2, out, out, HID, C_DIM);
}

// round 16
// speedup vs baseline: 2.4143x; 1.4849x over previous
#include <cuda_runtime.h>
#include <cuda_fp16.h>
#include <math.h>
#include <stdint.h>

// ---------------- problem constants ----------------
#define B_SZ   16
#define C_DIM  512
#define WS     7
#define NH     16
#define HD     32
#define HID    2048
#define NTOK   49
#define NWIN   64
#define M_TOK  50176
#define SCALE_F 0.17677669529663687f

// half-packed k-permutation within each 32-block:
// lane t (=(k&7)>>1) owns one 16B slot [16t..16t+15] per row containing its
// 8 halves: blk(k>>4): k={2t,2t+1} then k={8+2t,8+2t+1}.
// pos32(k) = 8*t + 4*blk + 2*hi + low  (blk=(k>>4)&1, hi=(k>>3)&1, low=k&1)
__host__ __device__ __forceinline__ int hperm(int c) {
    int t = (c & 7) >> 1;
    return (c & ~31) + 8 * t + 4 * ((c >> 4) & 1) + 2 * ((c >> 3) & 1) + (c & 1);
}

// ---------------- scratch (device globals; no allocation) ----------------
__device__ __half g_h[25690112];
__device__ __half g_q[25690112];
__device__ __half g_k[25690112];
__device__ __half g_v[25690112];
__device__ __half g_attn[25690112];
__device__ __half g_act[102760448];
__device__ __half g_wq[262144], g_wk[262144], g_wv[262144], g_wp[262144];
__device__ __half g_w1t[1048576];   // [2048][512]
__device__ __half g_w2t[1048576];   // [512][2048]

// ---------------- LayerNorm: fp16 k-permuted output ----------------------
__global__ void __launch_bounds__(128) ln_kernel(
    const float* __restrict__ x, const float* __restrict__ gw,
    const float* __restrict__ bw, __half* __restrict__ out)
{
    __shared__ float red[8];
    int row = blockIdx.x;
    int tid = threadIdx.x;
    const float4* xr = reinterpret_cast<const float4*>(x + (size_t)row * C_DIM);
    float4 v = xr[tid];
    float s  = v.x + v.y + v.z + v.w;
    float ss = v.x*v.x + v.y*v.y + v.z*v.z + v.w*v.w;
    #pragma unroll
    for (int o = 16; o > 0; o >>= 1) {
        s  += __shfl_xor_sync(0xFFFFFFFFu, s,  o);
        ss += __shfl_xor_sync(0xFFFFFFFFu, ss, o);
    }
    int warp = tid >> 5;
    if ((tid & 31) == 0) { red[warp] = s; red[4 + warp] = ss; }
    __syncthreads();
    float st  = red[0] + red[1] + red[2] + red[3];
    float sst = red[4] + red[5] + red[6] + red[7];
    float mu  = st * (1.0f / C_DIM);
    float var = sst * (1.0f / C_DIM) - mu * mu;
    float inv = rsqrtf(var + 1e-5f);
    float4 gv = reinterpret_cast<const float4*>(gw)[tid];
    float4 bv = reinterpret_cast<const float4*>(bw)[tid];
    float o0 = (v.x - mu) * inv * gv.x + bv.x;
    float o1 = (v.y - mu) * inv * gv.y + bv.y;
    float o2 = (v.z - mu) * inv * gv.z + bv.z;
    float o3 = (v.w - mu) * inv * gv.w + bv.w;
    int c0 = tid * 4;
    __half2* op = reinterpret_cast<__half2*>(out + (size_t)row * C_DIM);
    op[hperm(c0) >> 1]     = __floats2half2_rn(o0, o1);
    op[hperm(c0 + 2) >> 1] = __floats2half2_rn(o2, o3);
}

// ---------------- transpose W (K x N) -> Wt (N x K), permuted fp16 -------
__global__ void __launch_bounds__(256) transpose_kernel(
    const float* __restrict__ src, __half* __restrict__ dst, int R, int C)
{
    __shared__ float t[32][33];
    int bx = blockIdx.x * 32, by = blockIdx.y * 32;
    int tx = threadIdx.x & 31;
    int ty4 = (threadIdx.x >> 5) * 4;
    #pragma unroll
    for (int i = 0; i < 4; i++)
        t[ty4 + i][tx] = src[(size_t)(by + ty4 + i) * C + bx + tx];
    __syncthreads();
    #pragma unroll
    for (int i = 0; i < 4; i++) {
        int kk = by + tx;
        dst[(size_t)(bx + ty4 + i) * R + hperm(kk)] = __float2half_rn(t[tx][ty4 + i]);
    }
}

// ---------------- fp16 mma GEMM: 256x128 block, BK=32, 3-stage -----------
#define BMT 256
#define BNT 128
#define BKC 32                 // k per chunk

#define MODE_QKV  0
#define MODE_PROJ 1
#define MODE_FC1  2
#define MODE_FC2  3

#define A_BYTES (BMT * BKC * 2)   // 16384 per stage
#define B_BYTES (BNT * BKC * 2)   // 8192 per stage
#define STAGE_BYTES (A_BYTES + B_BYTES)         // 24576
#define SMEM_GEMM_BYTES (3 * STAGE_BYTES)       // 73728

__device__ __forceinline__ uint32_t smem_u32(const void* p) {
    uint32_t a;
    asm("{ .reg .u64 t; cvta.to.shared.u64 t, %1; cvt.u32.u64 %0, t; }"
        : "=r"(a) : "l"(p));
    return a;
}

__device__ __forceinline__ void mma_f16(
    float& c0, float& c1, float& c2, float& c3,
    uint32_t a0, uint32_t a1, uint32_t a2, uint32_t a3,
    uint32_t b0, uint32_t b1)
{
    asm volatile(
        "mma.sync.aligned.m16n8k16.row.col.f32.f16.f16.f32 "
        "{%0,%1,%2,%3}, {%4,%5,%6,%7}, {%8,%9}, {%0,%1,%2,%3};"
        : "+f"(c0), "+f"(c1), "+f"(c2), "+f"(c3)
        : "r"(a0), "r"(a1), "r"(a2), "r"(a3), "r"(b0), "r"(b1));
}

template<int MODE>
__global__ void __launch_bounds__(256) tgemm_kernel(
    const __half* __restrict__ A,     // M x K (fp16, k-permuted)
    const __half* __restrict__ Bt,    // Ncols x K (fp16, k-permuted)
    const float* __restrict__ bias,
    const float* __restrict__ resid,
    void* __restrict__ out_v,
    int K, int Ncols)
{
    extern __shared__ char smc[];
    uint32_t smb = smem_u32(smc);

    int tid  = threadIdx.x;
    int lane = tid & 31;
    int warp = tid >> 5;
    int gq   = lane >> 2;     // 0..7
    int tig  = lane & 3;      // 0..3
    int wm   = warp >> 1;     // 0..3 (64 rows each)
    int wn   = warp & 1;      // 0..1 (64 cols each)
    int m0 = blockIdx.y * BMT;
    int n0 = blockIdx.x * BNT;

    float acc[4][8][4];
    #pragma unroll
    for (int i = 0; i < 4; i++)
        #pragma unroll
        for (int j = 0; j < 8; j++)
            #pragma unroll
            for (int c = 0; c < 4; c++) acc[i][j][c] = 0.0f;

    const __half* a_base = A  + (size_t)m0 * K;
    const __half* b_base = Bt + (size_t)n0 * K;

    // per chunk: A 256 rows x 64B = 1024 x 16B (4/thr); B 128 x 64B = 512 (2/thr)
    auto load_chunk = [&](int c, int stage) {
        uint32_t sbase = smb + stage * STAGE_BYTES;
        #pragma unroll
        for (int j = 0; j < 4; j++) {
            int f = tid + j * 256;            // 0..1023
            int row = f >> 2, slot = f & 3;
            uint32_t saddr = sbase + row * 64 + slot * 16;
            const __half* g = a_base + (size_t)row * K + c * BKC + slot * 8;
            asm volatile("cp.async.cg.shared.global [%0], [%1], 16;"
                         :: "r"(saddr), "l"(g) : "memory");
        }
        #pragma unroll
        for (int j = 0; j < 2; j++) {
            int f = tid + j * 256;            // 0..511
            int row = f >> 2, slot = f & 3;
            uint32_t saddr = sbase + A_BYTES + row * 64 + slot * 16;
            const __half* g = b_base + (size_t)row * K + c * BKC + slot * 8;
            asm volatile("cp.async.cg.shared.global [%0], [%1], 16;"
                         :: "r"(saddr), "l"(g) : "memory");
        }
        asm volatile("cp.async.commit_group;" ::: "memory");
    };

    // uint4 layout per 16B fragment slot: .x = k{2t,2t+1} blk0, .y = k{8+2t,9+2t} blk0,
    //                                     .z = blk1 k-low pair, .w = blk1 k-high pair
    auto compute = [&](int stage) {
        const __half* Ab = reinterpret_cast<const __half*>(smc + stage * STAGE_BYTES);
        const __half* Bb = Ab + BMT * BKC;
        uint4 a0[4], a1[4];
        #pragma unroll
        for (int mt = 0; mt < 4; mt++) {
            int r0 = wm * 64 + mt * 16 + gq;
            a0[mt] = *reinterpret_cast<const uint4*>(Ab + r0 * BKC + tig * 8);
            a1[mt] = *reinterpret_cast<const uint4*>(Ab + (r0 + 8) * BKC + tig * 8);
        }
        #pragma unroll
        for (int half_ = 0; half_ < 2; half_++) {
            uint4 bf[4];
            #pragma unroll
            for (int q = 0; q < 4; q++) {
                int ncol = wn * 64 + (half_ * 4 + q) * 8 + gq;
                bf[q] = *reinterpret_cast<const uint4*>(Bb + ncol * BKC + tig * 8);
            }
            // k-block 0 for all 16 accumulators
            #pragma unroll
            for (int mt = 0; mt < 4; mt++)
                #pragma unroll
                for (int q = 0; q < 4; q++) {
                    int nt = half_ * 4 + q;
                    mma_f16(acc[mt][nt][0], acc[mt][nt][1], acc[mt][nt][2], acc[mt][nt][3],
                            a0[mt].x, a1[mt].x, a0[mt].y, a1[mt].y,
                            bf[q].x, bf[q].y);
                }
            // k-block 1
            #pragma unroll
            for (int mt = 0; mt < 4; mt++)
                #pragma unroll
                for (int q = 0; q < 4; q++) {
                    int nt = half_ * 4 + q;
                    mma_f16(acc[mt][nt][0], acc[mt][nt][1], acc[mt][nt][2], acc[mt][nt][3],
                            a0[mt].z, a1[mt].z, a0[mt].w, a1[mt].w,
                            bf[q].z, bf[q].w);
                }
        }
    };

    int nc = K / BKC;
    load_chunk(0, 0);
    load_chunk(1, 1);
    for (int c = 0; c < nc; c++) {
        int stage = c % 3;
        if (c + 1 < nc) asm volatile("cp.async.wait_group 1;" ::: "memory");
        else            asm volatile("cp.async.wait_group 0;" ::: "memory");
        __syncthreads();
        if (c + 2 < nc) load_chunk(c + 2, (c + 2) % 3);
        compute(stage);
    }

    // ---------------- epilogues ----------------
    #pragma unroll
    for (int mt = 0; mt < 4; mt++) {
        #pragma unroll
        for (int hh = 0; hh < 2; hh++) {
            int row = m0 + wm * 64 + mt * 16 + gq + hh * 8;
            if (MODE == MODE_QKV) {
                __half* out = (__half*)out_v;
                int bb = row / 3136;
                int l  = row - bb * 3136;
                int hr = l / 56;
                int wc = l - hr * 56;
                int gwin = bb * NWIN + (hr / WS) * 8 + (wc / WS);
                int n  = (hr % WS) * WS + (wc % WS);
                size_t ob = (size_t)gwin * (NH * NTOK * HD) + (size_t)n * HD;
                #pragma unroll
                for (int nt = 0; nt < 8; nt++) {
                    int col = n0 + wn * 64 + nt * 8 + 2 * tig;
                    float v0 = acc[mt][nt][2 * hh] + bias[col];
                    float v1 = acc[mt][nt][2 * hh + 1] + bias[col + 1];
                    int head = col >> 5, d = col & 31;
                    *reinterpret_cast<__half2*>(out + ob + (size_t)head * (NTOK * HD) + d)
                        = __floats2half2_rn(v0, v1);
                }
            } else if (MODE == MODE_FC1) {
                __half* out = (__half*)out_v;
                size_t ro = (size_t)row * Ncols;
                #pragma unroll
                for (int nt = 0; nt < 8; nt++) {
                    int col = n0 + wn * 64 + nt * 8 + 2 * tig;
                    float a0 = acc[mt][nt][2 * hh] + bias[col];
                    float a1 = acc[mt][nt][2 * hh + 1] + bias[col + 1];
                    float g0 = 0.5f * a0 * (1.0f + erff(a0 * 0.70710678118654752f));
                    float g1 = 0.5f * a1 * (1.0f + erff(a1 * 0.70710678118654752f));
                    *reinterpret_cast<__half2*>(out + ro + hperm(col))
                        = __floats2half2_rn(g0, g1);
                }
            } else {
                float* out = (float*)out_v;
                size_t ro = (size_t)row * Ncols;
                #pragma unroll
                for (int nt = 0; nt < 8; nt++) {
                    int col = n0 + wn * 64 + nt * 8 + 2 * tig;
                    float v0 = acc[mt][nt][2 * hh];
                    float v1 = acc[mt][nt][2 * hh + 1];
                    out[ro + col]     = v0 + bias[col]     + resid[ro + col];
                    out[ro + col + 1] = v1 + bias[col + 1] + resid[ro + col + 1];
                }
            }
        }
    }
}

// ---------------- attention: fp16 in, fp32 math, fp16 permuted out -------
__global__ void __launch_bounds__(128) attn_kernel(
    const __half* __restrict__ q, const __half* __restrict__ k,
    const __half* __restrict__ v, const float* __restrict__ rb,
    __half* __restrict__ out)
{
    __shared__ float qs[NTOK * 33];
    __shared__ float ks[NTOK * 33];
    __shared__ float vs[NTOK * 33];
    __shared__ float S[NTOK * NTOK];

    int head = blockIdx.x;
    int g    = blockIdx.y;
    int tid  = threadIdx.x;
    size_t base = ((size_t)g * NH + head) * (NTOK * HD);

    for (int i = tid; i < NTOK * HD; i += 128) {
        int n = i >> 5, d = i & 31;
        qs[n * 33 + d] = __half2float(q[base + i]);
        ks[n * 33 + d] = __half2float(k[base + i]);
        vs[n * 33 + d] = __half2float(v[base + i]);
    }
    __syncthreads();

    const float* rbh = rb + (size_t)head * NTOK * NTOK;
    for (int idx = tid; idx < NTOK * NTOK; idx += 128) {
        int n = idx / NTOK, m = idx - n * NTOK;
        float acc = 0.0f;
        #pragma unroll
        for (int d = 0; d < HD; d++)
            acc = fmaf(qs[n * 33 + d], ks[m * 33 + d], acc);
        S[idx] = acc * SCALE_F + rbh[idx];
    }
    __syncthreads();

    if (tid < NTOK) {
        float mx = -1e30f;
        #pragma unroll 7
        for (int m = 0; m < NTOK; m++) mx = fmaxf(mx, S[tid * NTOK + m]);
        float sum = 0.0f;
        #pragma unroll 7
        for (int m = 0; m < NTOK; m++) {
            float e = __expf(S[tid * NTOK + m] - mx);
            S[tid * NTOK + m] = e;
            sum += e;
        }
        float r = 1.0f / sum;
        #pragma unroll 7
        for (int m = 0; m < NTOK; m++) S[tid * NTOK + m] *= r;
    }
    __syncthreads();

    int bb = g >> 6;
    int wi = g & 63;
    int hr0 = (wi >> 3) * WS, wc0 = (wi & 7) * WS;
    for (int idx = tid; idx < NTOK * HD; idx += 128) {
        int n = idx >> 5, d = idx & 31;
        float acc = 0.0f;
        #pragma unroll 7
        for (int m = 0; m < NTOK; m++)
            acc = fmaf(S[n * NTOK + m], vs[m * 33 + d], acc);
        int hr = hr0 + n / WS, wc = wc0 + n % WS;
        size_t t = (size_t)bb * 3136 + (size_t)hr * 56 + wc;
        int chan = head * HD + d;
        out[t * C_DIM + hperm(chan)] = __float2half_rn(acc);
    }
}

// ---------------- launch ----------------
extern "C" void kernel_launch(void* const* d_in, const int* in_sizes, int n_in,
                              void* d_out, int out_size)
{
    const float* x    = (const float*)d_in[0];
    const float* Wq   = (const float*)d_in[1];
    const float* bq   = (const float*)d_in[2];
    const float* Wk   = (const float*)d_in[3];
    const float* bk   = (const float*)d_in[4];
    const float* Wv   = (const float*)d_in[5];
    const float* bv   = (const float*)d_in[6];
    const float* Wp   = (const float*)d_in[7];
    const float* bp   = (const float*)d_in[8];
    const float* rbias= (const float*)d_in[9];
    const float* g1   = (const float*)d_in[10];
    const float* b1   = (const float*)d_in[11];
    const float* g2   = (const float*)d_in[12];
    const float* b2   = (const float*)d_in[13];
    const float* W1   = (const float*)d_in[14];
    const float* bfc1 = (const float*)d_in[15];
    const float* W2   = (const float*)d_in[16];
    const float* bfc2 = (const float*)d_in[17];
    float* out = (float*)d_out;

    __half *h, *q, *k, *v, *attn, *act;
    __half *wq, *wk, *wv, *wp, *w1t, *w2t;
    cudaGetSymbolAddress((void**)&h,    g_h);
    cudaGetSymbolAddress((void**)&q,    g_q);
    cudaGetSymbolAddress((void**)&k,    g_k);
    cudaGetSymbolAddress((void**)&v,    g_v);
    cudaGetSymbolAddress((void**)&attn, g_attn);
    cudaGetSymbolAddress((void**)&act,  g_act);
    cudaGetSymbolAddress((void**)&wq,   g_wq);
    cudaGetSymbolAddress((void**)&wk,   g_wk);
    cudaGetSymbolAddress((void**)&wv,   g_wv);
    cudaGetSymbolAddress((void**)&wp,   g_wp);
    cudaGetSymbolAddress((void**)&w1t,  g_w1t);
    cudaGetSymbolAddress((void**)&w2t,  g_w2t);

    cudaFuncSetAttribute(tgemm_kernel<MODE_QKV>,  cudaFuncAttributeMaxDynamicSharedMemorySize, SMEM_GEMM_BYTES);
    cudaFuncSetAttribute(tgemm_kernel<MODE_PROJ>, cudaFuncAttributeMaxDynamicSharedMemorySize, SMEM_GEMM_BYTES);
    cudaFuncSetAttribute(tgemm_kernel<MODE_FC1>,  cudaFuncAttributeMaxDynamicSharedMemorySize, SMEM_GEMM_BYTES);
    cudaFuncSetAttribute(tgemm_kernel<MODE_FC2>,  cudaFuncAttributeMaxDynamicSharedMemorySize, SMEM_GEMM_BYTES);

    dim3 g512(4, M_TOK / BMT);      // N=512
    dim3 g2048(16, M_TOK / BMT);    // N=2048
    dim3 attn_grid(NH, B_SZ * NWIN);

    transpose_kernel<<<dim3(16, 16), 256>>>(Wq, wq, C_DIM, C_DIM);
    transpose_kernel<<<dim3(16, 16), 256>>>(Wk, wk, C_DIM, C_DIM);
    transpose_kernel<<<dim3(16, 16), 256>>>(Wv, wv, C_DIM, C_DIM);
    transpose_kernel<<<dim3(16, 16), 256>>>(Wp, wp, C_DIM, C_DIM);
    transpose_kernel<<<dim3(64, 16), 256>>>(W1, w1t, C_DIM, HID);
    transpose_kernel<<<dim3(16, 64), 256>>>(W2, w2t, HID, C_DIM);

    ln_kernel<<<M_TOK, 128>>>(x, g1, b1, h);
    tgemm_kernel<MODE_QKV><<<g512, 256, SMEM_GEMM_BYTES>>>(h, wq, bq, nullptr, q, C_DIM, C_DIM);
    tgemm_kernel<MODE_QKV><<<g512, 256, SMEM_GEMM_BYTES>>>(h, wk, bk, nullptr, k, C_DIM, C_DIM);
    tgemm_kernel<MODE_QKV><<<g512, 256, SMEM_GEMM_BYTES>>>(h, wv, bv, nullptr, v, C_DIM, C_DIM);
    attn_kernel<<<attn_grid, 128>>>(q, k, v, rbias, attn);
    tgemm_kernel<MODE_PROJ><<<g512, 256, SMEM_GEMM_BYTES>>>(attn, wp, bp, x, out, C_DIM, C_DIM);
    ln_kernel<<<M_TOK, 128>>>(out, g2, b2, h);
    tgemm_kernel<MODE_FC1><<<g2048, 256, SMEM_GEMM_BYTES>>>(h, w1t, bfc1, nullptr, act, C_DIM, HID);
    tgemm_kernel<MODE_FC2><<<g512, 256, SMEM_GEMM_BYTES>>>(act, w2t, bfc2, out, out, HID, C_DIM);
}